// round 3
// baseline (speedup 1.0000x reference)
#include <cuda_runtime.h>
#include <math.h>

#define NBATCH 4
#define NTOK   4096
#define NC     256
#define NH     8
#define ND     32
#define NPL    64
#define EPSF   1.1920929e-07f

// ---------------- scratch (device globals; no runtime alloc allowed) -------------
__device__ float g_qtmp[NBATCH*NTOK*NC];        // raw q gemm out (16 MB)
__device__ float g_q[NBATCH*NTOK*NC];           // q_scaled, layout (B,H,N,D) (16 MB)
__device__ float g_ltd[NBATCH*NH*NTOK*9];       // learnable-token dots + bias (4.7 MB)
__device__ float g_kv[NBATCH*NTOK*2*NC];        // kv, k-half l2-normalized in place (32 MB)
__device__ float g_gate[NBATCH*NTOK*NH];        // per-head gates (0.5 MB)
__device__ float g_xs[NBATCH*NTOK*NC];          // sr+gelu out (16 MB)
__device__ float g_pool[NBATCH*NPL*NC];         // pooled + LN (0.25 MB)
__device__ float g_kvp2[NBATCH*NPL*2*NC];       // pooled kv, k-half normalized (0.5 MB)
__device__ float g_cpbh[4096*512];              // cpb hidden (8 MB)
__device__ float g_cpb[4096*NH];                // cpb table (128 KB)
__device__ float g_attnout[NBATCH*NTOK*NC];     // pre-proj attention out (16 MB)

// ---------------- helpers --------------------------------------------------------
__device__ __forceinline__ float warpSum(float v){
  #pragma unroll
  for (int o=16;o>0;o>>=1) v += __shfl_xor_sync(0xffffffffu, v, o);
  return v;
}
__device__ __forceinline__ float warpMax(float v){
  #pragma unroll
  for (int o=16;o>0;o>>=1) v = fmaxf(v, __shfl_xor_sync(0xffffffffu, v, o));
  return v;
}

// ---------------- generic fp32 SGEMM: C = A(MxK) * W(NxK)^T + bias ----------------
template<bool GELU>
__global__ void __launch_bounds__(256)
sgemm_kernel(const float* __restrict__ A, const float* __restrict__ W,
             const float* __restrict__ bias, float* __restrict__ C,
             int M, int N, int K)
{
  __shared__ float As[16][132];
  __shared__ float Ws[16][68];
  const int m0 = blockIdx.y * 128;
  const int n0 = blockIdx.x * 64;
  const int tid = threadIdx.x;
  const int tx = tid & 15;   // -> 4 output cols
  const int ty = tid >> 4;   // -> 8 output rows
  float acc[8][4];
  #pragma unroll
  for (int i=0;i<8;i++){
    #pragma unroll
    for (int j=0;j<4;j++) acc[i][j]=0.f;
  }

  for (int k0=0;k0<K;k0+=16){
    #pragma unroll
    for (int u=0;u<2;u++){
      int f = tid + u*256;
      int row = f >> 2, cq = f & 3;
      float4 v = *(const float4*)(A + (m0+row)*K + k0 + cq*4);
      As[cq*4+0][row]=v.x; As[cq*4+1][row]=v.y;
      As[cq*4+2][row]=v.z; As[cq*4+3][row]=v.w;
    }
    {
      int row = tid >> 2, cq = tid & 3;
      float4 v = *(const float4*)(W + (n0+row)*K + k0 + cq*4);
      Ws[cq*4+0][row]=v.x; Ws[cq*4+1][row]=v.y;
      Ws[cq*4+2][row]=v.z; Ws[cq*4+3][row]=v.w;
    }
    __syncthreads();
    #pragma unroll
    for (int kk=0;kk<16;kk++){
      float a[8], w[4];
      #pragma unroll
      for (int i=0;i<8;i++) a[i]=As[kk][ty*8+i];
      #pragma unroll
      for (int j=0;j<4;j++) w[j]=Ws[kk][tx*4+j];
      #pragma unroll
      for (int i=0;i<8;i++){
        #pragma unroll
        for (int j=0;j<4;j++) acc[i][j] = fmaf(a[i], w[j], acc[i][j]);
      }
    }
    __syncthreads();
  }
  #pragma unroll
  for (int i=0;i<8;i++){
    int m = m0 + ty*8 + i;
    #pragma unroll
    for (int j=0;j<4;j++){
      int n = n0 + tx*4 + j;
      float v = acc[i][j] + bias[n];
      if (GELU) v = 0.5f*v*(1.f + erff(v*0.70710678118654752f));
      C[m*N + n] = v;
    }
  }
}

// ---------------- q post: l2norm, scale, learnable-token dots ---------------------
__global__ void __launch_bounds__(256)
qpost_kernel(const float* __restrict__ temp, const float* __restrict__ qe,
             const float* __restrict__ lt, const float* __restrict__ lb)
{
  int w = (blockIdx.x * 256 + threadIdx.x) >> 5;   // (b*8+h)*4096+n
  int lane = threadIdx.x & 31;
  int n = w & 4095;
  int bh = w >> 12;
  int h = bh & 7, b = bh >> 3;
  float qv = g_qtmp[(b*4096+n)*256 + h*32 + lane];
  float ss = warpSum(qv*qv);
  float qn = qv / fmaxf(sqrtf(ss), EPSF);
  int yi = n >> 6, xj = n & 63;
  int ch = min(yi+1,63) - max(yi-1,0) + 1;
  int cw = min(xj+1,63) - max(xj-1,0) + 1;
  float sls = logf((float)(ch*cw) + 64.f);
  float sp = log1pf(expf(temp[h]));
  g_q[w*32 + lane] = (qn + qe[h*32+lane]) * sp * sls;
  #pragma unroll
  for (int l=0;l<9;l++){
    float p = warpSum(qn * lt[h*288 + lane*9 + l]);
    if (lane == l) g_ltd[w*9 + l] = p + lb[h*9+l];
  }
}

// ---------------- kv post: l2-normalize k half per head (in place) ---------------
__global__ void __launch_bounds__(256)
kvpost_kernel()
{
  int w = (blockIdx.x*256 + threadIdx.x) >> 5;  // row*8+h
  int lane = threadIdx.x & 31;
  int h = w & 7, row = w >> 3;
  float* p = g_kv + row*512 + h*32 + lane;
  float v = *p;
  float ss = warpSum(v*v);
  *p = v / fmaxf(sqrtf(ss), EPSF);
}

__global__ void __launch_bounds__(256)
kvp2post_kernel()
{
  int w = (blockIdx.x*256 + threadIdx.x) >> 5;  // row*8+h, row < 256
  int lane = threadIdx.x & 31;
  int h = w & 7, row = w >> 3;
  float* p = g_kvp2 + row*512 + h*32 + lane;
  float v = *p;
  float ss = warpSum(v*v);
  *p = v / fmaxf(sqrtf(ss), EPSF);
}

// ---------------- gating (routed top-2, shared, w0) ------------------------------
__global__ void __launch_bounds__(256)
gates_kernel(const float* __restrict__ x, const float* __restrict__ wg,
             const float* __restrict__ wg0, const float* __restrict__ wg1)
{
  int w = (blockIdx.x*256 + threadIdx.x) >> 5;   // row = b*4096+n
  int lane = threadIdx.x & 31;
  const float* xr = x + w*256;
  float xv[8];
  {
    float4 a = *(const float4*)(xr + lane*8);
    float4 c = *(const float4*)(xr + lane*8 + 4);
    xv[0]=a.x; xv[1]=a.y; xv[2]=a.z; xv[3]=a.w;
    xv[4]=c.x; xv[5]=c.y; xv[6]=c.z; xv[7]=c.w;
  }
  float d[10];
  #pragma unroll
  for (int r=0;r<10;r++){
    const float* wr = (r<4) ? (wg + r*256) : ((r<6) ? (wg0 + (r-4)*256) : (wg1 + (r-6)*256));
    float pp = 0.f;
    #pragma unroll
    for (int k=0;k<8;k++) pp = fmaf(xv[k], wr[lane*8+k], pp);
    d[r] = warpSum(pp);
  }
  if (lane == 0){
    // routed gates: softmax(d[0..3]), top-2, renorm, *2
    float m = fmaxf(fmaxf(d[0],d[1]),fmaxf(d[2],d[3]));
    float e[4], se=0.f;
    #pragma unroll
    for (int k=0;k<4;k++){ e[k]=expf(d[k]-m); se+=e[k]; }
    float gg[4];
    #pragma unroll
    for (int k=0;k<4;k++) gg[k]=e[k]/se;
    int i0=0;
    #pragma unroll
    for (int k=1;k<4;k++) if (gg[k]>gg[i0]) i0=k;
    int i1=-1;
    #pragma unroll
    for (int k=0;k<4;k++) if (k!=i0 && (i1<0 || gg[k]>gg[i1])) i1=k;
    float s2 = fmaxf(gg[i0]+gg[i1], EPSF);
    float routed[4]={0.f,0.f,0.f,0.f};
    routed[i0]=gg[i0]/s2*2.f; routed[i1]=gg[i1]/s2*2.f;
    // w0: softmax(d[4..5]) * 2
    float m0 = fmaxf(d[4],d[5]);
    float e4=expf(d[4]-m0), e5=expf(d[5]-m0);
    float w00 = e4/(e4+e5)*2.f, w01 = e5/(e4+e5)*2.f;
    // shared: softmax(d[6..9]) * 4
    float m1 = fmaxf(fmaxf(d[6],d[7]),fmaxf(d[8],d[9]));
    float es[4], ss2=0.f;
    #pragma unroll
    for (int k=0;k<4;k++){ es[k]=expf(d[6+k]-m1); ss2+=es[k]; }
    float* gp = g_gate + w*8;
    #pragma unroll
    for (int k=0;k<4;k++) gp[k]   = w00 * (es[k]/ss2*4.f);
    #pragma unroll
    for (int k=0;k<4;k++) gp[4+k] = w01 * routed[k];
  }
}

// ---------------- 8x8 avg pool + LayerNorm ---------------------------------------
__global__ void __launch_bounds__(256)
pool_ln_kernel(const float* __restrict__ ng, const float* __restrict__ nb)
{
  int b = blockIdx.x >> 6, p = blockIdx.x & 63;
  int c = threadIdx.x;
  int pi = p >> 3, pj = p & 7;
  float s = 0.f;
  #pragma unroll
  for (int si=0; si<8; si++){
    int rowbase = b*4096 + (pi*8+si)*64 + pj*8;
    #pragma unroll
    for (int sj=0; sj<8; sj++)
      s += g_xs[(rowbase + sj)*256 + c];
  }
  float v = s * (1.f/64.f);
  __shared__ float shs[8], shq[8];
  int lane = c & 31, wid = c >> 5;
  float s1 = warpSum(v), sq = warpSum(v*v);
  if (lane==0){ shs[wid]=s1; shq[wid]=sq; }
  __syncthreads();
  float tot=0.f, totq=0.f;
  #pragma unroll
  for (int i=0;i<8;i++){ tot+=shs[i]; totq+=shq[i]; }
  float mu = tot*(1.f/256.f);
  float var = totq*(1.f/256.f) - mu*mu;
  g_pool[(b*64+p)*256 + c] = (v-mu)*rsqrtf(var+1e-5f)*ng[c] + nb[c];
}

// ---------------- cpb MLP --------------------------------------------------------
__global__ void __launch_bounds__(256)
cpb_hidden_kernel(const float* __restrict__ ct, const float* __restrict__ w1,
                  const float* __restrict__ b1)
{
  int tid = blockIdx.x*256 + threadIdx.x;
  if (tid >= 4096*512) return;
  int t = tid >> 9, j = tid & 511;
  float v = fmaf(ct[t*2], w1[j*2], fmaf(ct[t*2+1], w1[j*2+1], b1[j]));
  g_cpbh[tid] = fmaxf(v, 0.f);
}

__global__ void __launch_bounds__(256)
cpb_out_kernel(const float* __restrict__ w2, const float* __restrict__ b2)
{
  int t = (blockIdx.x*256 + threadIdx.x) >> 5;   // table row
  int lane = threadIdx.x & 31;
  float s[8] = {0,0,0,0,0,0,0,0};
  #pragma unroll
  for (int it=0; it<16; it++){
    float hv = g_cpbh[t*512 + it*32 + lane];
    #pragma unroll
    for (int h=0;h<8;h++) s[h] = fmaf(hv, w2[h*512 + it*32 + lane], s[h]);
  }
  #pragma unroll
  for (int h=0;h<8;h++){
    float tot = warpSum(s[h]);
    if (lane == 0) g_cpb[t*8 + h] = tot + b2[h];
  }
}

// ---------------- fused local+pool attention -------------------------------------
__global__ void __launch_bounds__(256)
attn_kernel(const float* __restrict__ rpb, const int* __restrict__ rpi)
{
  __shared__ float ks[32*64];   // k_pool transposed [d][p]
  __shared__ float vs[64*32];   // v_pool [p][d]
  const int bh = blockIdx.y;
  const int h = bh & 7, b = bh >> 3;
  const int tid = threadIdx.x;
  for (int idx = tid; idx < 2048; idx += 256){
    int p = idx >> 5, d = idx & 31;
    const float* base = g_kvp2 + (b*64+p)*512 + h*32 + d;
    ks[d*64+p] = base[0];
    vs[idx]    = base[256];
  }
  __syncthreads();
  const int warp = tid >> 5, lane = tid & 31;
  float rpbl[9];
  #pragma unroll
  for (int l=0;l<9;l++) rpbl[l] = rpb[h*9+l];

  for (int it=0; it<8; it++){
    int n = blockIdx.x*64 + warp*8 + it;
    int yi = n >> 6, xj = n & 63;
    float qs = g_q[((b*8+h)*4096 + n)*32 + lane];
    // local window scores (zero-padded -> score = rpb, v = 0)
    float sloc[9]; int nloc[9];
    #pragma unroll
    for (int l=0;l<9;l++){
      int y  = yi + l/3 - 1;
      int x2 = xj + l%3 - 1;
      bool val = ((unsigned)y < 64u) && ((unsigned)x2 < 64u);
      int nl = y*64 + x2;
      nloc[l] = val ? nl : -1;
      float kd = val ? g_kv[(b*4096+nl)*512 + h*32 + lane] : 0.f;
      sloc[l] = warpSum(qs*kd) + rpbl[l];
    }
    // pool scores: lane handles p=lane and p=lane+32
    const int* rr = rpi + n*64;
    int ia = rr[lane], ib = rr[lane+32];
    float s0 = g_cpb[ia*8+h];
    float s1 = g_cpb[ib*8+h];
    #pragma unroll
    for (int d=0; d<32; d++){
      float qd = __shfl_sync(0xffffffffu, qs, d);
      s0 = fmaf(qd, ks[d*64+lane],    s0);
      s1 = fmaf(qd, ks[d*64+lane+32], s1);
    }
    // softmax over 73
    float m = fmaxf(s0, s1);
    #pragma unroll
    for (int l=0;l<9;l++) m = fmaxf(m, sloc[l]);
    m = warpMax(m);
    float el[9], suml = 0.f;
    #pragma unroll
    for (int l=0;l<9;l++){ el[l] = expf(sloc[l]-m); suml += el[l]; }
    float e0 = expf(s0-m), e1 = expf(s1-m);
    float inv = 1.f / (suml + warpSum(e0+e1));
    // local AV (+ learnable-token modulation)
    const float* ltdp = g_ltd + ((b*8+h)*4096 + n)*9;
    float outv = 0.f;
    #pragma unroll
    for (int l=0;l<9;l++){
      float al = el[l]*inv + ltdp[l];
      if (nloc[l] >= 0)
        outv = fmaf(al, g_kv[(b*4096+nloc[l])*512 + 256 + h*32 + lane], outv);
    }
    // pool AV
    #pragma unroll
    for (int p=0;p<32;p++){
      float ap = __shfl_sync(0xffffffffu, e0, p) * inv;
      outv = fmaf(ap, vs[p*32+lane], outv);
    }
    #pragma unroll
    for (int p=0;p<32;p++){
      float ap = __shfl_sync(0xffffffffu, e1, p) * inv;
      outv = fmaf(ap, vs[(p+32)*32+lane], outv);
    }
    float gate = g_gate[(b*4096+n)*8 + h];
    g_attnout[(b*4096+n)*256 + h*32 + lane] = outv * gate;
  }
}

// ---------------- launch ---------------------------------------------------------
extern "C" void kernel_launch(void* const* d_in, const int* in_sizes, int n_in,
                              void* d_out, int out_size)
{
  const float* x      = (const float*)d_in[0];
  const float* ctab   = (const float*)d_in[1];
  const float* q_w    = (const float*)d_in[2];
  const float* q_b    = (const float*)d_in[3];
  const float* kv_w   = (const float*)d_in[4];
  const float* kv_b   = (const float*)d_in[5];
  const float* temp   = (const float*)d_in[6];
  const float* qe     = (const float*)d_in[7];
  const float* rpb    = (const float*)d_in[8];
  const float* lt     = (const float*)d_in[9];
  const float* lb     = (const float*)d_in[10];
  const float* cpb1_w = (const float*)d_in[11];
  const float* cpb1_b = (const float*)d_in[12];
  const float* cpb2_w = (const float*)d_in[13];
  const float* cpb2_b = (const float*)d_in[14];
  const float* sr_w   = (const float*)d_in[15];
  const float* sr_b   = (const float*)d_in[16];
  const float* norm_g = (const float*)d_in[17];
  const float* norm_b = (const float*)d_in[18];
  const float* wg_w   = (const float*)d_in[19];
  const float* wg0_w  = (const float*)d_in[20];
  const float* wg1_w  = (const float*)d_in[21];
  const float* proj_w = (const float*)d_in[22];
  const float* proj_b = (const float*)d_in[23];
  const int*   rpi    = (const int*)d_in[24];
  float* out = (float*)d_out;

  float *p_qtmp, *p_kv, *p_xs, *p_pool, *p_kvp2, *p_attnout;
  cudaGetSymbolAddress((void**)&p_qtmp,    g_qtmp);
  cudaGetSymbolAddress((void**)&p_kv,      g_kv);
  cudaGetSymbolAddress((void**)&p_xs,      g_xs);
  cudaGetSymbolAddress((void**)&p_pool,    g_pool);
  cudaGetSymbolAddress((void**)&p_kvp2,    g_kvp2);
  cudaGetSymbolAddress((void**)&p_attnout, g_attnout);

  const int M = NBATCH*NTOK;   // 16384

  // gating (only needs x)
  gates_kernel<<<2048, 256>>>(x, wg_w, wg0_w, wg1_w);
  // q path
  sgemm_kernel<false><<<dim3(4,128), 256>>>(x, q_w, q_b, p_qtmp, M, 256, 256);
  qpost_kernel<<<16384, 256>>>(temp, qe, lt, lb);
  // kv path
  sgemm_kernel<false><<<dim3(8,128), 256>>>(x, kv_w, kv_b, p_kv, M, 512, 256);
  kvpost_kernel<<<16384, 256>>>();
  // pooled path
  sgemm_kernel<true><<<dim3(4,128), 256>>>(x, sr_w, sr_b, p_xs, M, 256, 256);
  pool_ln_kernel<<<256, 256>>>(norm_g, norm_b);
  sgemm_kernel<false><<<dim3(8,2), 256>>>(p_pool, kv_w, kv_b, p_kvp2, 256, 512, 256);
  kvp2post_kernel<<<256, 256>>>();
  // cpb MLP
  cpb_hidden_kernel<<<8192, 256>>>(ctab, cpb1_w, cpb1_b);
  cpb_out_kernel<<<512, 256>>>(cpb2_w, cpb2_b);
  // fused attention
  attn_kernel<<<dim3(64, 32), 256>>>(rpb, rpi);
  // projection
  sgemm_kernel<false><<<dim3(4,128), 256>>>(p_attnout, proj_w, proj_b, out, M, 256, 256);
}